// round 9
// baseline (speedup 1.0000x reference)
#include <cuda_runtime.h>
#include <cuda_bf16.h>
#include <math.h>

// Problem constants
#define B_  4
#define L_  1024
#define D_  1024
#define N_  16
#define R_  64
#define ROWS (B_ * L_)      // 4096
#define F_  (4 * D_)        // 4096

// -------------------- scratch (static device globals; no allocation) --------
__device__ float g_h0[ROWS * D_];     // softplus(LN1(x))            16 MB
__device__ float g_delta[ROWS * D_];  // softplus(delta proj)        16 MB
__device__ float g_bc[ROWS * 32];     // per-row B (16) then C (16)   0.5 MB
__device__ float g_h[ROWS * D_];      // h after SSM residual        16 MB
__device__ float g_mn[ROWS * D_];     // LN2(h)                      16 MB
__device__ float g_act[ROWS * F_];    // gelu(mn @ W_fc^T)           64 MB

// -------------------- helpers ------------------------------------------------
__device__ __forceinline__ float softplusf(float x) {
    // stable: max(x,0) + log1p(exp(-|x|))
    return fmaxf(x, 0.0f) + log1pf(expf(-fabsf(x)));
}

__device__ __forceinline__ float geluf(float x) {
    const float c = 0.7978845608028654f; // sqrt(2/pi)
    float x3 = x * x * x;
    return 0.5f * x * (1.0f + tanhf(c * (x + 0.044715f * x3)));
}

// block-wide sum for 256 threads; sred must have >= 33 floats
__device__ __forceinline__ float blk_sum256(float s, float* sred) {
    __syncthreads();   // protect sred from previous use
    int lane = threadIdx.x & 31, w = threadIdx.x >> 5;
    #pragma unroll
    for (int o = 16; o; o >>= 1) s += __shfl_xor_sync(0xffffffffu, s, o);
    if (lane == 0) sred[w] = s;
    __syncthreads();
    if (threadIdx.x < 32) {
        float v = (threadIdx.x < 8) ? sred[threadIdx.x] : 0.0f;
        #pragma unroll
        for (int o = 4; o; o >>= 1) v += __shfl_xor_sync(0xffffffffu, v, o);
        if (threadIdx.x == 0) sred[32] = v;
    }
    __syncthreads();
    return sred[32];
}

// -------------------- kernel 1: LN1 + softplus + dbc proj + delta proj -------
// one block (256 threads) per row (b*L + l)
__global__ __launch_bounds__(256)
void k_ln1_proj(const float* __restrict__ x,
                const float* __restrict__ ln1_w,
                const float* __restrict__ W_dbc,   // (96, 1024)
                const float* __restrict__ W_dt,    // (1024, 64)
                const float* __restrict__ b_dt) {
    __shared__ float sh[D_];
    __shared__ float sdl[R_];
    __shared__ float sred[33];
    const int row = blockIdx.x;
    const int tid = threadIdx.x;
    const float* xr = x + (size_t)row * D_;

    float s = 0.0f;
    for (int j = tid; j < D_; j += 256) { float v = xr[j]; sh[j] = v; s += v; }
    float mu = blk_sum256(s, sred) * (1.0f / D_);

    float s2 = 0.0f;
    for (int j = tid; j < D_; j += 256) { float c = sh[j] - mu; s2 += c * c; }
    float var = blk_sum256(s2, sred) * (1.0f / D_);
    float rstd = rsqrtf(var + 1e-5f);

    for (int j = tid; j < D_; j += 256) {
        float v = (sh[j] - mu) * rstd * ln1_w[j];
        float h0 = softplusf(v);
        sh[j] = h0;
        g_h0[(size_t)row * D_ + j] = h0;
    }
    __syncthreads();

    // dbc = h0 @ W_dbc^T : 96 outputs, 8 warps x 12
    int warp = tid >> 5, lane = tid & 31;
    for (int e = warp; e < R_ + 2 * N_; e += 8) {
        const float* w = W_dbc + (size_t)e * D_;
        float acc = 0.0f;
        for (int j = lane; j < D_; j += 32) acc = fmaf(sh[j], w[j], acc);
        #pragma unroll
        for (int o = 16; o; o >>= 1) acc += __shfl_xor_sync(0xffffffffu, acc, o);
        if (lane == 0) {
            if (e < R_) sdl[e] = acc;
            else        g_bc[row * 32 + (e - R_)] = acc;  // B then C
        }
    }
    __syncthreads();

    // delta = softplus(delta_lr @ W_dt^T + b_dt)
    for (int d = tid; d < D_; d += 256) {
        const float* wd = W_dt + (size_t)d * R_;
        float acc = b_dt[d];
        #pragma unroll
        for (int r = 0; r < R_; r++) acc = fmaf(sdl[r], wd[r], acc);
        g_delta[(size_t)row * D_ + d] = softplusf(acc);
    }
}

// -------------------- kernel 2: selective scan -------------------------------
// one lane per (d, n) state; 16 lanes per scan; 2 scans per warp.
// grid = B_ * (D_/16) = 256 blocks of 256 threads (16 scans / block).
__global__ __launch_bounds__(256)
void k_scan(const float* __restrict__ A_log,  // (1024, 16)
            const float* __restrict__ Dp) {
    const int b    = blockIdx.x >> 6;           // 0..3
    const int dblk = blockIdx.x & 63;           // 0..63
    const int warp = threadIdx.x >> 5;
    const int lane = threadIdx.x & 31;
    const int d    = dblk * 16 + (warp << 1) + (lane >> 4);
    const int n    = lane & 15;

    const float Afac = -expf(A_log[d * N_ + n]);
    const float Dpv  = Dp[d];

    float h = 0.0f;
    size_t base   = ((size_t)b * L_) * D_ + d;
    int    row32  = (b * L_) * 32;

    #pragma unroll 2
    for (int l = 0; l < L_; l++) {
        float dl = g_delta[base];
        float xv = g_h0[base];
        float Bn = g_bc[row32 + n];
        float Cn = g_bc[row32 + 16 + n];
        float dA = __expf(dl * Afac);
        h = fmaf(dA, h, dl * xv * Bn);
        float y = h * Cn;
        #pragma unroll
        for (int o = 8; o; o >>= 1) y += __shfl_xor_sync(0xffffffffu, y, o);
        if (n == 0) g_h[base] = xv + y + xv * Dpv;   // h0 + (y + h0*Dp)
        base  += D_;
        row32 += 32;
    }
}

// -------------------- kernel 3: LN2 ------------------------------------------
__global__ __launch_bounds__(256)
void k_ln2(const float* __restrict__ ln2_w) {
    __shared__ float sh[D_];
    __shared__ float sred[33];
    const int row = blockIdx.x;
    const int tid = threadIdx.x;
    const float* hr = g_h + (size_t)row * D_;

    float s = 0.0f;
    for (int j = tid; j < D_; j += 256) { float v = hr[j]; sh[j] = v; s += v; }
    float mu = blk_sum256(s, sred) * (1.0f / D_);
    float s2 = 0.0f;
    for (int j = tid; j < D_; j += 256) { float c = sh[j] - mu; s2 += c * c; }
    float var = blk_sum256(s2, sred) * (1.0f / D_);
    float rstd = rsqrtf(var + 1e-5f);
    for (int j = tid; j < D_; j += 256)
        g_mn[(size_t)row * D_ + j] = (sh[j] - mu) * rstd * ln2_w[j];
}

// -------------------- SGEMM: C = A(MxK,row) * B(NxK,row)^T -------------------
// BM=BN=128, BK=8, 256 threads, 8x8 per thread, register-prefetched loads.
// EPI=0: C = gelu(acc)   -> Cout
// EPI=1: C = res + acc   -> Cout
template <int EPI>
__global__ __launch_bounds__(256)
void k_sgemm(const float* __restrict__ A, const float* __restrict__ Bm,
             float* __restrict__ Cout, const float* __restrict__ res,
             int K, int ldc) {
    __shared__ float As[8 * 128];
    __shared__ float Bs[8 * 128];

    const int tid = threadIdx.x;
    const int tx = tid & 15;        // 0..15
    const int ty = tid >> 4;        // 0..15
    const int r  = tid >> 1;        // load row 0..127
    const int cg = (tid & 1) * 4;   // load col group

    const float* Aload = A  + ((size_t)blockIdx.y * 128 + r) * K + cg;
    const float* Bload = Bm + ((size_t)blockIdx.x * 128 + r) * K + cg;

    float acc[8][8];
    #pragma unroll
    for (int i = 0; i < 8; i++)
        #pragma unroll
        for (int j = 0; j < 8; j++) acc[i][j] = 0.0f;

    float4 pa = *(const float4*)(Aload);
    float4 pb = *(const float4*)(Bload);

    for (int kt = 0; kt < K; kt += 8) {
        // store prefetched tile (transposed) to smem
        As[(cg + 0) * 128 + r] = pa.x;
        As[(cg + 1) * 128 + r] = pa.y;
        As[(cg + 2) * 128 + r] = pa.z;
        As[(cg + 3) * 128 + r] = pa.w;
        Bs[(cg + 0) * 128 + r] = pb.x;
        Bs[(cg + 1) * 128 + r] = pb.y;
        Bs[(cg + 2) * 128 + r] = pb.z;
        Bs[(cg + 3) * 128 + r] = pb.w;
        __syncthreads();

        if (kt + 8 < K) {
            pa = *(const float4*)(Aload + kt + 8);
            pb = *(const float4*)(Bload + kt + 8);
        }

        #pragma unroll
        for (int kk = 0; kk < 8; kk++) {
            float4 a0 = *(const float4*)(&As[kk * 128 + ty * 8]);
            float4 a1 = *(const float4*)(&As[kk * 128 + ty * 8 + 4]);
            float4 b0 = *(const float4*)(&Bs[kk * 128 + tx * 8]);
            float4 b1 = *(const float4*)(&Bs[kk * 128 + tx * 8 + 4]);
            float av[8] = {a0.x, a0.y, a0.z, a0.w, a1.x, a1.y, a1.z, a1.w};
            float bv[8] = {b0.x, b0.y, b0.z, b0.w, b1.x, b1.y, b1.z, b1.w};
            #pragma unroll
            for (int i = 0; i < 8; i++)
                #pragma unroll
                for (int j = 0; j < 8; j++)
                    acc[i][j] = fmaf(av[i], bv[j], acc[i][j]);
        }
        __syncthreads();
    }

    // epilogue
    #pragma unroll
    for (int i = 0; i < 8; i++) {
        int row = blockIdx.y * 128 + ty * 8 + i;
        #pragma unroll
        for (int jv = 0; jv < 2; jv++) {
            int col = blockIdx.x * 128 + tx * 8 + jv * 4;
            float4 o;
            if (EPI == 0) {
                o.x = geluf(acc[i][jv * 4 + 0]);
                o.y = geluf(acc[i][jv * 4 + 1]);
                o.z = geluf(acc[i][jv * 4 + 2]);
                o.w = geluf(acc[i][jv * 4 + 3]);
            } else {
                float4 rr = *(const float4*)(&res[(size_t)row * ldc + col]);
                o.x = rr.x + acc[i][jv * 4 + 0];
                o.y = rr.y + acc[i][jv * 4 + 1];
                o.z = rr.z + acc[i][jv * 4 + 2];
                o.w = rr.w + acc[i][jv * 4 + 3];
            }
            *(float4*)(&Cout[(size_t)row * ldc + col]) = o;
        }
    }
}

// -------------------- launch -------------------------------------------------
extern "C" void kernel_launch(void* const* d_in, const int* in_sizes, int n_in,
                              void* d_out, int out_size) {
    const float* x      = (const float*)d_in[0];
    const float* ln1_w  = (const float*)d_in[1];
    const float* ln2_w  = (const float*)d_in[2];
    const float* W_dbc  = (const float*)d_in[3];
    const float* W_dt   = (const float*)d_in[4];
    const float* b_dt   = (const float*)d_in[5];
    const float* A_log  = (const float*)d_in[6];
    const float* Dp     = (const float*)d_in[7];
    const float* W_fc   = (const float*)d_in[8];
    const float* W_proj = (const float*)d_in[9];
    float* out = (float*)d_out;

    float *h0p, *hp, *mnp, *actp;
    cudaGetSymbolAddress((void**)&h0p,  g_h0);
    cudaGetSymbolAddress((void**)&hp,   g_h);
    cudaGetSymbolAddress((void**)&mnp,  g_mn);
    cudaGetSymbolAddress((void**)&actp, g_act);

    // 1. LN1 + softplus + projections
    k_ln1_proj<<<ROWS, 256>>>(x, ln1_w, W_dbc, W_dt, b_dt);

    // 2. selective scan (+ SSM skip + residual) -> g_h
    k_scan<<<B_ * (D_ / 16), 256>>>(A_log, Dp);

    // 3. LN2 -> g_mn
    k_ln2<<<ROWS, 256>>>(ln2_w);

    // 4. GEMM1 + gelu: g_act = gelu(g_mn @ W_fc^T)   (4096 x 4096 x 1024)
    {
        dim3 grid(F_ / 128, ROWS / 128);
        k_sgemm<0><<<grid, 256>>>(mnp, W_fc, actp, nullptr, D_, F_);
    }

    // 5. GEMM2 + residual: out = g_h + g_act @ W_proj^T  (4096 x 1024 x 4096)
    {
        dim3 grid(D_ / 128, ROWS / 128);
        k_sgemm<1><<<grid, 256>>>(actp, W_proj, out, hp, F_, D_);
    }
}

// round 10
// speedup vs baseline: 2.4553x; 2.4553x over previous
#include <cuda_runtime.h>
#include <cuda_bf16.h>
#include <math.h>
#include <stdint.h>

// Problem constants
#define B_  4
#define L_  1024
#define D_  1024
#define N_  16
#define R_  64
#define ROWS (B_ * L_)      // 4096
#define F_  (4 * D_)        // 4096

// -------------------- scratch (static device globals; no allocation) --------
__device__ float g_h0[ROWS * D_];     // softplus(LN1(x))
__device__ float g_delta[ROWS * D_];  // softplus(delta proj)
__device__ float g_bc[ROWS * 32];     // per-row B (16) then C (16)
__device__ float g_h[ROWS * D_];      // h after SSM residual
__device__ float g_mn[ROWS * D_];     // LN2(h)
__device__ float g_act[ROWS * F_];    // gelu(mn @ W_fc^T)

// -------------------- helpers ------------------------------------------------
__device__ __forceinline__ float softplusf(float x) {
    return fmaxf(x, 0.0f) + log1pf(expf(-fabsf(x)));
}

__device__ __forceinline__ float geluf(float x) {
    const float c = 0.7978845608028654f; // sqrt(2/pi)
    float x3 = x * x * x;
    return 0.5f * x * (1.0f + tanhf(c * (x + 0.044715f * x3)));
}

__device__ __forceinline__ float blk_sum256(float s, float* sred) {
    __syncthreads();
    int lane = threadIdx.x & 31, w = threadIdx.x >> 5;
    #pragma unroll
    for (int o = 16; o; o >>= 1) s += __shfl_xor_sync(0xffffffffu, s, o);
    if (lane == 0) sred[w] = s;
    __syncthreads();
    if (threadIdx.x < 32) {
        float v = (threadIdx.x < 8) ? sred[threadIdx.x] : 0.0f;
        #pragma unroll
        for (int o = 4; o; o >>= 1) v += __shfl_xor_sync(0xffffffffu, v, o);
        if (threadIdx.x == 0) sred[32] = v;
    }
    __syncthreads();
    return sred[32];
}

// tf32 helpers
__device__ __forceinline__ uint32_t f2tf32(float x) {
    uint32_t u;
    asm("cvt.rna.tf32.f32 %0, %1;" : "=r"(u) : "f"(x));
    return u;
}

__device__ __forceinline__ void mma_tf32(float* d, const uint32_t* a, const uint32_t* b) {
    asm volatile(
        "mma.sync.aligned.m16n8k8.row.col.f32.tf32.tf32.f32 "
        "{%0,%1,%2,%3}, {%4,%5,%6,%7}, {%8,%9}, {%0,%1,%2,%3};\n"
        : "+f"(d[0]), "+f"(d[1]), "+f"(d[2]), "+f"(d[3])
        : "r"(a[0]), "r"(a[1]), "r"(a[2]), "r"(a[3]),
          "r"(b[0]), "r"(b[1]));
}

// -------------------- kernel 1: LN1 + softplus + dbc proj + delta proj -------
__global__ __launch_bounds__(256)
void k_ln1_proj(const float* __restrict__ x,
                const float* __restrict__ ln1_w,
                const float* __restrict__ W_dbc,   // (96, 1024)
                const float* __restrict__ W_dt,    // (1024, 64)
                const float* __restrict__ b_dt) {
    __shared__ float sh[D_];
    __shared__ float sdl[R_];
    __shared__ float sred[33];
    const int row = blockIdx.x;
    const int tid = threadIdx.x;
    const float* xr = x + (size_t)row * D_;

    float s = 0.0f;
    for (int j = tid; j < D_; j += 256) { float v = xr[j]; sh[j] = v; s += v; }
    float mu = blk_sum256(s, sred) * (1.0f / D_);

    float s2 = 0.0f;
    for (int j = tid; j < D_; j += 256) { float c = sh[j] - mu; s2 += c * c; }
    float var = blk_sum256(s2, sred) * (1.0f / D_);
    float rstd = rsqrtf(var + 1e-5f);

    for (int j = tid; j < D_; j += 256) {
        float v = (sh[j] - mu) * rstd * ln1_w[j];
        float h0 = softplusf(v);
        sh[j] = h0;
        g_h0[(size_t)row * D_ + j] = h0;
    }
    __syncthreads();

    int warp = tid >> 5, lane = tid & 31;
    for (int e = warp; e < R_ + 2 * N_; e += 8) {
        const float* w = W_dbc + (size_t)e * D_;
        float acc = 0.0f;
        for (int j = lane; j < D_; j += 32) acc = fmaf(sh[j], w[j], acc);
        #pragma unroll
        for (int o = 16; o; o >>= 1) acc += __shfl_xor_sync(0xffffffffu, acc, o);
        if (lane == 0) {
            if (e < R_) sdl[e] = acc;
            else        g_bc[row * 32 + (e - R_)] = acc;
        }
    }
    __syncthreads();

    for (int d = tid; d < D_; d += 256) {
        const float* wd = W_dt + (size_t)d * R_;
        float acc = b_dt[d];
        #pragma unroll
        for (int r = 0; r < R_; r++) acc = fmaf(sdl[r], wd[r], acc);
        g_delta[(size_t)row * D_ + d] = softplusf(acc);
    }
}

// -------------------- kernel 2: selective scan -------------------------------
__global__ __launch_bounds__(256)
void k_scan(const float* __restrict__ A_log,
            const float* __restrict__ Dp) {
    const int b    = blockIdx.x >> 6;
    const int dblk = blockIdx.x & 63;
    const int warp = threadIdx.x >> 5;
    const int lane = threadIdx.x & 31;
    const int d    = dblk * 16 + (warp << 1) + (lane >> 4);
    const int n    = lane & 15;

    const float Afac = -expf(A_log[d * N_ + n]);
    const float Dpv  = Dp[d];

    float h = 0.0f;
    size_t base   = ((size_t)b * L_) * D_ + d;
    int    row32  = (b * L_) * 32;

    #pragma unroll 2
    for (int l = 0; l < L_; l++) {
        float dl = g_delta[base];
        float xv = g_h0[base];
        float Bn = g_bc[row32 + n];
        float Cn = g_bc[row32 + 16 + n];
        float dA = __expf(dl * Afac);
        h = fmaf(dA, h, dl * xv * Bn);
        float y = h * Cn;
        #pragma unroll
        for (int o = 8; o; o >>= 1) y += __shfl_xor_sync(0xffffffffu, y, o);
        if (n == 0) g_h[base] = xv + y + xv * Dpv;
        base  += D_;
        row32 += 32;
    }
}

// -------------------- kernel 3: LN2 ------------------------------------------
__global__ __launch_bounds__(256)
void k_ln2(const float* __restrict__ ln2_w) {
    __shared__ float sh[D_];
    __shared__ float sred[33];
    const int row = blockIdx.x;
    const int tid = threadIdx.x;
    const float* hr = g_h + (size_t)row * D_;

    float s = 0.0f;
    for (int j = tid; j < D_; j += 256) { float v = hr[j]; sh[j] = v; s += v; }
    float mu = blk_sum256(s, sred) * (1.0f / D_);
    float s2 = 0.0f;
    for (int j = tid; j < D_; j += 256) { float c = sh[j] - mu; s2 += c * c; }
    float var = blk_sum256(s2, sred) * (1.0f / D_);
    float rstd = rsqrtf(var + 1e-5f);
    for (int j = tid; j < D_; j += 256)
        g_mn[(size_t)row * D_ + j] = (sh[j] - mu) * rstd * ln2_w[j];
}

// -------------------- tf32 tensor-core GEMM: C = A(MxK) * B(NxK)^T -----------
// BM=BN=128, BK=16, 256 threads = 8 warps (2 M x 4 N), warp tile 64x32,
// mma.sync.m16n8k8.tf32 with fp32 accumulate. Explicit cvt.rna.tf32 at the
// smem store (removes truncation bias). Smem row stride 20 floats:
// fragment-load banks = grp*20 + tig (+4/+8k) mod 32 -> conflict-free.
// EPI=0: C = gelu(acc); EPI=1: C = res + acc.
template <int EPI>
__global__ __launch_bounds__(256)
void k_mma_tf32(const float* __restrict__ A, const float* __restrict__ Bm,
                float* __restrict__ Cout, const float* __restrict__ res,
                int K, int ldc) {
    constexpr int KP = 20;
    __shared__ float As[128 * KP];
    __shared__ float Bs[128 * KP];

    const int tid  = threadIdx.x;
    const int lane = tid & 31;
    const int wid  = tid >> 5;
    const int grp  = lane >> 2;     // 0..7
    const int tig  = lane & 3;      // 0..3
    const int wm   = (wid & 1) * 64;   // warp M offset
    const int wn   = (wid >> 1) * 32;  // warp N offset

    // global-load mapping: 64 rows x 16 cols per pass, two passes per tile
    const int lrow = tid >> 2;        // 0..63
    const int lcol = (tid & 3) * 4;   // 0,4,8,12

    const float* Ag = A  + ((size_t)blockIdx.y * 128 + lrow) * K + lcol;
    const float* Bg = Bm + ((size_t)blockIdx.x * 128 + lrow) * K + lcol;
    const size_t half = (size_t)64 * K;

    float acc[4][4][4];
    #pragma unroll
    for (int mt = 0; mt < 4; mt++)
        #pragma unroll
        for (int nt = 0; nt < 4; nt++)
            #pragma unroll
            for (int i = 0; i < 4; i++) acc[mt][nt][i] = 0.0f;

    float4 pa0 = *(const float4*)(Ag);
    float4 pa1 = *(const float4*)(Ag + half);
    float4 pb0 = *(const float4*)(Bg);
    float4 pb1 = *(const float4*)(Bg + half);

    for (int kt = 0; kt < K; kt += 16) {
        // store prefetched tiles with tf32 rounding
        {
            uint32_t* pA0 = (uint32_t*)&As[lrow * KP + lcol];
            uint32_t* pA1 = (uint32_t*)&As[(lrow + 64) * KP + lcol];
            uint32_t* pB0 = (uint32_t*)&Bs[lrow * KP + lcol];
            uint32_t* pB1 = (uint32_t*)&Bs[(lrow + 64) * KP + lcol];
            pA0[0] = f2tf32(pa0.x); pA0[1] = f2tf32(pa0.y); pA0[2] = f2tf32(pa0.z); pA0[3] = f2tf32(pa0.w);
            pA1[0] = f2tf32(pa1.x); pA1[1] = f2tf32(pa1.y); pA1[2] = f2tf32(pa1.z); pA1[3] = f2tf32(pa1.w);
            pB0[0] = f2tf32(pb0.x); pB0[1] = f2tf32(pb0.y); pB0[2] = f2tf32(pb0.z); pB0[3] = f2tf32(pb0.w);
            pB1[0] = f2tf32(pb1.x); pB1[1] = f2tf32(pb1.y); pB1[2] = f2tf32(pb1.z); pB1[3] = f2tf32(pb1.w);
        }
        __syncthreads();

        if (kt + 16 < K) {
            pa0 = *(const float4*)(Ag + kt + 16);
            pa1 = *(const float4*)(Ag + half + kt + 16);
            pb0 = *(const float4*)(Bg + kt + 16);
            pb1 = *(const float4*)(Bg + half + kt + 16);
        }

        #pragma unroll
        for (int ks = 0; ks < 2; ks++) {
            const int k0 = ks * 8 + tig;
            uint32_t af[4][4], bf[4][2];
            #pragma unroll
            for (int mt = 0; mt < 4; mt++) {
                int r = wm + mt * 16 + grp;
                af[mt][0] = __float_as_uint(As[r * KP + k0]);
                af[mt][1] = __float_as_uint(As[(r + 8) * KP + k0]);
                af[mt][2] = __float_as_uint(As[r * KP + k0 + 4]);
                af[mt][3] = __float_as_uint(As[(r + 8) * KP + k0 + 4]);
            }
            #pragma unroll
            for (int nt = 0; nt < 4; nt++) {
                int r = wn + nt * 8 + grp;
                bf[nt][0] = __float_as_uint(Bs[r * KP + k0]);
                bf[nt][1] = __float_as_uint(Bs[r * KP + k0 + 4]);
            }
            #pragma unroll
            for (int mt = 0; mt < 4; mt++)
                #pragma unroll
                for (int nt = 0; nt < 4; nt++)
                    mma_tf32(acc[mt][nt], af[mt], bf[nt]);
        }
        __syncthreads();
    }

    // epilogue: c0,c1 -> (grp, 2*tig .. +1); c2,c3 -> (grp+8, same cols)
    #pragma unroll
    for (int mt = 0; mt < 4; mt++) {
        #pragma unroll
        for (int nt = 0; nt < 4; nt++) {
            int row0 = blockIdx.y * 128 + wm + mt * 16 + grp;
            int col  = blockIdx.x * 128 + wn + nt * 8 + tig * 2;
            float* c = acc[mt][nt];
            if (EPI == 0) {
                float2 o0 = {geluf(c[0]), geluf(c[1])};
                float2 o1 = {geluf(c[2]), geluf(c[3])};
                *(float2*)(&Cout[(size_t)row0 * ldc + col])       = o0;
                *(float2*)(&Cout[(size_t)(row0 + 8) * ldc + col]) = o1;
            } else {
                float2 r0 = *(const float2*)(&res[(size_t)row0 * ldc + col]);
                float2 r1 = *(const float2*)(&res[(size_t)(row0 + 8) * ldc + col]);
                float2 o0 = {r0.x + c[0], r0.y + c[1]};
                float2 o1 = {r1.x + c[2], r1.y + c[3]};
                *(float2*)(&Cout[(size_t)row0 * ldc + col])       = o0;
                *(float2*)(&Cout[(size_t)(row0 + 8) * ldc + col]) = o1;
            }
        }
    }
}

// -------------------- launch -------------------------------------------------
extern "C" void kernel_launch(void* const* d_in, const int* in_sizes, int n_in,
                              void* d_out, int out_size) {
    const float* x      = (const float*)d_in[0];
    const float* ln1_w  = (const float*)d_in[1];
    const float* ln2_w  = (const float*)d_in[2];
    const float* W_dbc  = (const float*)d_in[3];
    const float* W_dt   = (const float*)d_in[4];
    const float* b_dt   = (const float*)d_in[5];
    const float* A_log  = (const float*)d_in[6];
    const float* Dp     = (const float*)d_in[7];
    const float* W_fc   = (const float*)d_in[8];
    const float* W_proj = (const float*)d_in[9];
    float* out = (float*)d_out;

    float *hp, *mnp, *actp;
    cudaGetSymbolAddress((void**)&hp,   g_h);
    cudaGetSymbolAddress((void**)&mnp,  g_mn);
    cudaGetSymbolAddress((void**)&actp, g_act);

    // 1. LN1 + softplus + projections
    k_ln1_proj<<<ROWS, 256>>>(x, ln1_w, W_dbc, W_dt, b_dt);

    // 2. selective scan (+ SSM skip + residual) -> g_h
    k_scan<<<B_ * (D_ / 16), 256>>>(A_log, Dp);

    // 3. LN2 -> g_mn
    k_ln2<<<ROWS, 256>>>(ln2_w);

    // 4. GEMM1 + gelu (tf32 MMA): g_act = gelu(g_mn @ W_fc^T)
    {
        dim3 grid(F_ / 128, ROWS / 128);
        k_mma_tf32<0><<<grid, 256>>>(mnp, W_fc, actp, nullptr, D_, F_);
    }

    // 5. GEMM2 + residual (tf32 MMA): out = g_h + g_act @ W_proj^T
    {
        dim3 grid(D_ / 128, ROWS / 128);
        k_mma_tf32<1><<<grid, 256>>>(actp, W_proj, out, hp, F_, D_);
    }
}

// round 15
// speedup vs baseline: 4.9700x; 2.0241x over previous
#include <cuda_runtime.h>
#include <cuda_bf16.h>
#include <math.h>
#include <stdint.h>

// Problem constants
#define B_  4
#define L_  1024
#define D_  1024
#define N_  16
#define R_  64
#define ROWS (B_ * L_)      // 4096
#define F_  (4 * D_)        // 4096

// -------------------- scratch (static device globals; no allocation) --------
__device__ float g_h0[ROWS * D_];     // softplus(LN1(x))
__device__ float g_dlr[ROWS * R_];    // delta low-rank (4096 x 64)
__device__ float g_delta[ROWS * D_];  // softplus(delta proj)
__device__ float g_bc[ROWS * 32];     // per-row B (16) then C (16)
__device__ float g_h[ROWS * D_];      // h after SSM residual
__device__ float g_mn[ROWS * D_];     // LN2(h)
__device__ float g_act[ROWS * F_];    // gelu(mn @ W_fc^T)

// -------------------- helpers ------------------------------------------------
__device__ __forceinline__ float softplusf(float x) {
    return fmaxf(x, 0.0f) + log1pf(expf(-fabsf(x)));
}

__device__ __forceinline__ float geluf(float x) {
    const float c = 0.7978845608028654f; // sqrt(2/pi)
    float x3 = x * x * x;
    return 0.5f * x * (1.0f + tanhf(c * (x + 0.044715f * x3)));
}

__device__ __forceinline__ float blk_sum256(float s, float* sred) {
    __syncthreads();
    int lane = threadIdx.x & 31, w = threadIdx.x >> 5;
    #pragma unroll
    for (int o = 16; o; o >>= 1) s += __shfl_xor_sync(0xffffffffu, s, o);
    if (lane == 0) sred[w] = s;
    __syncthreads();
    if (threadIdx.x < 32) {
        float v = (threadIdx.x < 8) ? sred[threadIdx.x] : 0.0f;
        #pragma unroll
        for (int o = 4; o; o >>= 1) v += __shfl_xor_sync(0xffffffffu, v, o);
        if (threadIdx.x == 0) sred[32] = v;
    }
    __syncthreads();
    return sred[32];
}

__device__ __forceinline__ uint32_t f2tf32(float x) {
    uint32_t u;
    asm("cvt.rna.tf32.f32 %0, %1;" : "=r"(u) : "f"(x));
    return u;
}

__device__ __forceinline__ void mma_tf32(float* d, const uint32_t* a, const uint32_t* b) {
    asm volatile(
        "mma.sync.aligned.m16n8k8.row.col.f32.tf32.tf32.f32 "
        "{%0,%1,%2,%3}, {%4,%5,%6,%7}, {%8,%9}, {%0,%1,%2,%3};\n"
        : "+f"(d[0]), "+f"(d[1]), "+f"(d[2]), "+f"(d[3])
        : "r"(a[0]), "r"(a[1]), "r"(a[2]), "r"(a[3]),
          "r"(b[0]), "r"(b[1]));
}

// -------------------- kernel: LN1 + softplus ---------------------------------
__global__ __launch_bounds__(256)
void k_ln1(const float* __restrict__ x, const float* __restrict__ w) {
    __shared__ float sred[33];
    const int row = blockIdx.x, tid = threadIdx.x;
    float4 v = ((const float4*)(x + (size_t)row * D_))[tid];
    float s = v.x + v.y + v.z + v.w;
    float mu = blk_sum256(s, sred) * (1.0f / D_);
    float cx = v.x - mu, cy = v.y - mu, cz = v.z - mu, cw = v.w - mu;
    float s2 = cx * cx + cy * cy + cz * cz + cw * cw;
    float var = blk_sum256(s2, sred) * (1.0f / D_);
    float rstd = rsqrtf(var + 1e-5f);
    float4 wv = ((const float4*)w)[tid];
    float4 o;
    o.x = softplusf(cx * rstd * wv.x);
    o.y = softplusf(cy * rstd * wv.y);
    o.z = softplusf(cz * rstd * wv.z);
    o.w = softplusf(cw * rstd * wv.w);
    ((float4*)(g_h0 + (size_t)row * D_))[tid] = o;
}

// -------------------- kernel: LN2 --------------------------------------------
__global__ __launch_bounds__(256)
void k_ln2(const float* __restrict__ w) {
    __shared__ float sred[33];
    const int row = blockIdx.x, tid = threadIdx.x;
    float4 v = ((const float4*)(g_h + (size_t)row * D_))[tid];
    float s = v.x + v.y + v.z + v.w;
    float mu = blk_sum256(s, sred) * (1.0f / D_);
    float cx = v.x - mu, cy = v.y - mu, cz = v.z - mu, cw = v.w - mu;
    float s2 = cx * cx + cy * cy + cz * cz + cw * cw;
    float var = blk_sum256(s2, sred) * (1.0f / D_);
    float rstd = rsqrtf(var + 1e-5f);
    float4 wv = ((const float4*)w)[tid];
    float4 o = {cx * rstd * wv.x, cy * rstd * wv.y, cz * rstd * wv.z, cw * rstd * wv.w};
    ((float4*)(g_mn + (size_t)row * D_))[tid] = o;
}

// -------------------- kernel: selective scan ---------------------------------
__global__ __launch_bounds__(256)
void k_scan(const float* __restrict__ A_log,
            const float* __restrict__ Dp) {
    const int b    = blockIdx.x >> 6;
    const int dblk = blockIdx.x & 63;
    const int warp = threadIdx.x >> 5;
    const int lane = threadIdx.x & 31;
    const int d    = dblk * 16 + (warp << 1) + (lane >> 4);
    const int n    = lane & 15;

    const float Afac = -expf(A_log[d * N_ + n]);
    const float Dpv  = Dp[d];

    float h = 0.0f;
    size_t base   = ((size_t)b * L_) * D_ + d;
    int    row32  = (b * L_) * 32;

    #pragma unroll 2
    for (int l = 0; l < L_; l++) {
        float dl = g_delta[base];
        float xv = g_h0[base];
        float Bn = g_bc[row32 + n];
        float Cn = g_bc[row32 + 16 + n];
        float dA = __expf(dl * Afac);
        h = fmaf(dA, h, dl * xv * Bn);
        float y = h * Cn;
        #pragma unroll
        for (int o = 8; o; o >>= 1) y += __shfl_xor_sync(0xffffffffu, y, o);
        if (n == 0) g_h[base] = xv + y + xv * Dpv;
        base  += D_;
        row32 += 32;
    }
}

// ==================== tf32 MMA GEMM v2: C = A(MxK) * B(NxK)^T ================
// 128x128 tile, BK=16, 8 warps (2M x 4N), warp tile 64x32, double-buffered.
// Fragment-permuted smem: chunk c = (rb*2+ks)*32 + lane (16B each), swizzled
// cs = c ^ ((c>>3)&7). Lane's A-fragment = one LDS.128; B chunk packs two
// 8-n fragments -> one LDS.128 serves 2 n-tiles.
// EPI 0: gelu(acc)            -> Cout[row*ldc+col]
// EPI 1: aux[..] + acc        -> Cout           (aux = residual, same ldc)
// EPI 2: softplus(acc+aux[col]) -> Cout         (aux = bias vector)
// EPI 3: cols<64 -> g_dlr, 64..95 -> g_bc (nvalid=96 guards B rows/cols)
template <int EPI>
__global__ __launch_bounds__(256, 2)
void k_mma(const float* __restrict__ A, const float* __restrict__ Bm,
           float* __restrict__ Cout, const float* __restrict__ aux,
           int K, int ldc, int nvalid) {
    __shared__ float smem[8192];   // [buf][A 2048 | B 2048]

    const int tid  = threadIdx.x;
    const int lane = tid & 31;
    const int wid  = tid >> 5;
    const int grp  = lane >> 2;
    const int tig  = lane & 3;
    const int wm   = (wid & 1) * 64;
    const int wn   = (wid >> 1) * 32;

    // ---- global load mapping: rows lrow & lrow+64, cols lcol..lcol+3 ----
    const int lrow = tid >> 2;
    const int lcol = (tid & 3) * 4;
    const float* Ag = A  + ((size_t)blockIdx.y * 128 + lrow) * K + lcol;
    const float* Bg = Bm + ((size_t)blockIdx.x * 128 + lrow) * K + lcol;
    const size_t halfA = (size_t)64 * K;
    const int brow0 = blockIdx.x * 128 + lrow;
    const int brow1 = brow0 + 64;
    const bool bok0 = (brow0 < nvalid);
    const bool bok1 = (brow1 < nvalid);

    // ---- store addressing (per thread, tile-invariant) ----
    const int ihS  = (lrow >> 3) & 1;
    const int grpS = lrow & 7;
    const int ksS  = lcol >> 3;
    const int khS  = (lcol >> 2) & 1;
    const int Cb   = ((lrow >> 4) * 2 + ksS) * 32 + grpS * 4;  // +j
    const int eS   = ihS + 2 * khS;

    // ---- load addressing (per warp, tile-invariant) ----
    int cA0 = ((wm >> 4) * 2 + 0) * 32 + lane;
    int cA1 = ((wm >> 4) * 2 + 1) * 32 + lane;
    int cB0 = ((wn >> 4) * 2 + 0) * 32 + lane;
    int cB1 = ((wn >> 4) * 2 + 1) * 32 + lane;
    const int csA0 = (cA0 ^ ((cA0 >> 3) & 7)) * 4;
    const int csA1 = (cA1 ^ ((cA1 >> 3) & 7)) * 4;
    const int csB0 = (cB0 ^ ((cB0 >> 3) & 7)) * 4 + 2048;
    const int csB1 = (cB1 ^ ((cB1 >> 3) & 7)) * 4 + 2048;

    float acc[4][4][4];
    #pragma unroll
    for (int mt = 0; mt < 4; mt++)
        #pragma unroll
        for (int nt = 0; nt < 4; nt++)
            #pragma unroll
            for (int i = 0; i < 4; i++) acc[mt][nt][i] = 0.0f;

    const float4 z4 = {0.f, 0.f, 0.f, 0.f};
    float4 pa0, pa1, pb0, pb1;

    auto ldg_tile = [&](int t) {
        pa0 = *(const float4*)(Ag + t * 16);
        pa1 = *(const float4*)(Ag + halfA + t * 16);
        pb0 = bok0 ? *(const float4*)(Bg + t * 16) : z4;
        pb1 = bok1 ? *(const float4*)(Bg + halfA + t * 16) : z4;
    };
    auto sts_tile = [&](int buf) {
        int bo = buf * 4096;
        float va[4] = {pa0.x, pa0.y, pa0.z, pa0.w};
        float vb[4] = {pa1.x, pa1.y, pa1.z, pa1.w};
        float vc[4] = {pb0.x, pb0.y, pb0.z, pb0.w};
        float vd[4] = {pb1.x, pb1.y, pb1.z, pb1.w};
        #pragma unroll
        for (int j = 0; j < 4; j++) {
            int c  = Cb + j;
            int cs = (c ^ ((c >> 3) & 7)) * 4 + eS;
            smem[bo + cs]               = __uint_as_float(f2tf32(va[j]));
            smem[bo + cs + 1024]        = __uint_as_float(f2tf32(vb[j]));
            smem[bo + cs + 2048]        = __uint_as_float(f2tf32(vc[j]));
            smem[bo + cs + 2048 + 1024] = __uint_as_float(f2tf32(vd[j]));
        }
    };

    const int T = K >> 4;
    ldg_tile(0);
    sts_tile(0);
    ldg_tile(1);
    __syncthreads();

    int buf = 0;
    for (int kt = 0; kt < T; kt++) {
        if (kt + 1 < T) sts_tile(buf ^ 1);
        if (kt + 2 < T) ldg_tile(kt + 2);

        const int bo = buf * 4096;
        #pragma unroll
        for (int ks = 0; ks < 2; ks++) {
            const int ao = bo + (ks ? csA1 : csA0);
            const int bo2 = bo + (ks ? csB1 : csB0);
            float4 bv0 = *(const float4*)&smem[bo2];
            float4 bv1 = *(const float4*)&smem[bo2 + 256];
            uint32_t bfr[4][2];
            bfr[0][0] = __float_as_uint(bv0.x); bfr[0][1] = __float_as_uint(bv0.z);
            bfr[1][0] = __float_as_uint(bv0.y); bfr[1][1] = __float_as_uint(bv0.w);
            bfr[2][0] = __float_as_uint(bv1.x); bfr[2][1] = __float_as_uint(bv1.z);
            bfr[3][0] = __float_as_uint(bv1.y); bfr[3][1] = __float_as_uint(bv1.w);
            #pragma unroll
            for (int mt = 0; mt < 4; mt++) {
                float4 av = *(const float4*)&smem[ao + mt * 256];
                uint32_t afr[4] = {__float_as_uint(av.x), __float_as_uint(av.y),
                                   __float_as_uint(av.z), __float_as_uint(av.w)};
                #pragma unroll
                for (int nt = 0; nt < 4; nt++)
                    mma_tf32(acc[mt][nt], afr, bfr[nt]);
            }
        }
        __syncthreads();
        buf ^= 1;
    }

    // ---- epilogue ----
    #pragma unroll
    for (int mt = 0; mt < 4; mt++) {
        #pragma unroll
        for (int nt = 0; nt < 4; nt++) {
            int row0 = blockIdx.y * 128 + wm + mt * 16 + grp;
            int col  = blockIdx.x * 128 + wn + nt * 8 + tig * 2;
            float* c = acc[mt][nt];
            if (EPI == 0) {
                float2 o0 = {geluf(c[0]), geluf(c[1])};
                float2 o1 = {geluf(c[2]), geluf(c[3])};
                *(float2*)(&Cout[(size_t)row0 * ldc + col])       = o0;
                *(float2*)(&Cout[(size_t)(row0 + 8) * ldc + col]) = o1;
            } else if (EPI == 1) {
                float2 r0 = *(const float2*)(&aux[(size_t)row0 * ldc + col]);
                float2 r1 = *(const float2*)(&aux[(size_t)(row0 + 8) * ldc + col]);
                float2 o0 = {r0.x + c[0], r0.y + c[1]};
                float2 o1 = {r1.x + c[2], r1.y + c[3]};
                *(float2*)(&Cout[(size_t)row0 * ldc + col])       = o0;
                *(float2*)(&Cout[(size_t)(row0 + 8) * ldc + col]) = o1;
            } else if (EPI == 2) {
                float b0 = aux[col], b1 = aux[col + 1];
                float2 o0 = {softplusf(c[0] + b0), softplusf(c[1] + b1)};
                float2 o1 = {softplusf(c[2] + b0), softplusf(c[3] + b1)};
                *(float2*)(&Cout[(size_t)row0 * ldc + col])       = o0;
                *(float2*)(&Cout[(size_t)(row0 + 8) * ldc + col]) = o1;
            } else { // EPI == 3: split dlr / bc
                if (col < R_) {
                    *(float2*)(&Cout[(size_t)row0 * R_ + col])       = make_float2(c[0], c[1]);
                    *(float2*)(&Cout[(size_t)(row0 + 8) * R_ + col]) = make_float2(c[2], c[3]);
                } else if (col < R_ + 2 * N_) {
                    int cc = col - R_;
                    *(float2*)(&g_bc[row0 * 32 + cc])       = make_float2(c[0], c[1]);
                    *(float2*)(&g_bc[(row0 + 8) * 32 + cc]) = make_float2(c[2], c[3]);
                }
            }
        }
    }
}

// -------------------- launch -------------------------------------------------
extern "C" void kernel_launch(void* const* d_in, const int* in_sizes, int n_in,
                              void* d_out, int out_size) {
    const float* x      = (const float*)d_in[0];
    const float* ln1_w  = (const float*)d_in[1];
    const float* ln2_w  = (const float*)d_in[2];
    const float* W_dbc  = (const float*)d_in[3];
    const float* W_dt   = (const float*)d_in[4];
    const float* b_dt   = (const float*)d_in[5];
    const float* A_log  = (const float*)d_in[6];
    const float* Dp     = (const float*)d_in[7];
    const float* W_fc   = (const float*)d_in[8];
    const float* W_proj = (const float*)d_in[9];
    float* out = (float*)d_out;

    float *h0p, *dlrp, *deltap, *hp, *mnp, *actp;
    cudaGetSymbolAddress((void**)&h0p,    g_h0);
    cudaGetSymbolAddress((void**)&dlrp,   g_dlr);
    cudaGetSymbolAddress((void**)&deltap, g_delta);
    cudaGetSymbolAddress((void**)&hp,     g_h);
    cudaGetSymbolAddress((void**)&mnp,    g_mn);
    cudaGetSymbolAddress((void**)&actp,   g_act);

    const int BIG = 1 << 30;

    // 1. LN1 + softplus -> g_h0
    k_ln1<<<ROWS, 256>>>(x, ln1_w);

    // 2. dbc projection (MMA, N padded 96->128): g_dlr + g_bc
    k_mma<3><<<dim3(1, ROWS / 128), 256>>>(h0p, W_dbc, dlrp, nullptr, D_, 0, R_ + 2 * N_);

    // 3. delta = softplus(dlr @ W_dt^T + b_dt)  (MMA, K=64)
    k_mma<2><<<dim3(D_ / 128, ROWS / 128), 256>>>(dlrp, W_dt, deltap, b_dt, R_, D_, BIG);

    // 4. selective scan (+ SSM skip + residual) -> g_h
    k_scan<<<B_ * (D_ / 16), 256>>>(A_log, Dp);

    // 5. LN2 -> g_mn
    k_ln2<<<ROWS, 256>>>(ln2_w);

    // 6. GEMM1 + gelu: g_act = gelu(g_mn @ W_fc^T)
    k_mma<0><<<dim3(F_ / 128, ROWS / 128), 256>>>(mnp, W_fc, actp, nullptr, D_, F_, BIG);

    // 7. GEMM2 + residual: out = g_h + g_act @ W_proj^T
    k_mma<1><<<dim3(D_ / 128, ROWS / 128), 256>>>(actp, W_proj, out, hp, F_, D_, BIG);
}